// round 7
// baseline (speedup 1.0000x reference)
#include <cuda_runtime.h>
#include <math.h>
#include <float.h>

#define Bsz 16
#define Tsz 128
#define Hsz 512
#define Vsz 32000
#define STEPS 127
#define MR (STEPS*Bsz)   /* 2032 */
#define NB 128

/* ---------- device scratch ---------- */
__device__ float g_vt[Bsz*Tsz*Hsz];
__device__ float g_xe[MR*Hsz];
__device__ float g_gix[MR*3*Hsz];
__device__ float g_Hs[MR*Hsz];
__device__ float g_q[Bsz*Hsz];
__device__ float g_gh[Bsz*3*Hsz];
__device__ float g_scores[Bsz*Tsz];
__device__ float g_ctxT[Hsz*Bsz];
__device__ float g_hT[2*Hsz*Bsz];
__device__ float g_a2[512*4096];      /* A transposed + duplicated pairs */
__device__ float g_bt[512*32000];     /* B transposed [k][n] */
__device__ volatile int g_flags[NB];

/* ---------- helpers ---------- */
typedef unsigned long long ull;
__device__ __forceinline__ ull pk2(float lo, float hi){
    ull r; asm("mov.b64 %0,{%1,%2};" : "=l"(r) : "f"(lo), "f"(hi)); return r;
}
__device__ __forceinline__ void upk2(ull v, float& lo, float& hi){
    asm("mov.b64 {%0,%1},%2;" : "=f"(lo), "=f"(hi) : "l"(v));
}
__device__ __forceinline__ void fma2(ull& d, ull a, ull b){
    asm("fma.rn.f32x2 %0,%1,%2,%0;" : "+l"(d) : "l"(a), "l"(b));
}
__device__ __forceinline__ ull addp(ull a, ull b){
    ull r; asm("add.rn.f32x2 %0,%1,%2;" : "=l"(r) : "l"(a), "l"(b)); return r;
}
__device__ __forceinline__ ull wred64(ull v){
    #pragma unroll
    for (int o = 16; o > 0; o >>= 1)
        v = addp(v, __shfl_xor_sync(0xffffffffu, v, o));
    return v;
}
__device__ __forceinline__ float wred(float v){
    #pragma unroll
    for (int o = 16; o > 0; o >>= 1) v += __shfl_xor_sync(0xffffffffu, v, o);
    return v;
}
__device__ __forceinline__ float wmax(float v){
    #pragma unroll
    for (int o = 16; o > 0; o >>= 1) v = fmaxf(v, __shfl_xor_sync(0xffffffffu, v, o));
    return v;
}
__device__ __forceinline__ float ftanh(float x){
    float cx = fminf(fmaxf(x, -9.f), 9.f);
    float e = __expf(2.f*cx);
    return __fdividef(e - 1.f, e + 1.f);
}
__device__ __forceinline__ float fsig(float x){
    float cx = fminf(fmaxf(x, -30.f), 30.f);
    return __fdividef(1.f, 1.f + __expf(-cx));
}

/* ---------- init ---------- */
__global__ void k_h0(const float* __restrict__ eh){
    int i = blockIdx.x*256 + threadIdx.x;
    if (i < Hsz*Bsz){
        int b = i >> 9, k = i & 511;
        g_hT[k*16 + b] = eh[i];
    }
    if (blockIdx.x == 0 && threadIdx.x < NB) g_flags[threadIdx.x] = 0;
}

__global__ void k_gather(const float* __restrict__ emb, const int* __restrict__ tgt){
    int m = blockIdx.x;
    int s = m >> 4, b = m & 15;
    int tok = (s == 0) ? 1 : tgt[b*Tsz + s];
    const float4* src = (const float4*)(emb + (size_t)tok*Hsz);
    float4* dst = (float4*)(g_xe + (size_t)m*Hsz);
    for (int i = threadIdx.x; i < Hsz/4; i += blockDim.x) dst[i] = src[i];
}

__global__ void k_zero(float* __restrict__ out){
    int i = blockIdx.x*256 + threadIdx.x;
    int b = i / Vsz, v = i - b*Vsz;
    out[(size_t)b*Tsz*Vsz + v] = 0.0f;
}

__global__ void k_tail(float* __restrict__ out){
    int i = blockIdx.x*256 + threadIdx.x;
    int b = i >> 9, k = i & 511;
    out[(size_t)Bsz*Tsz*Vsz + i] = g_Hs[(size_t)((STEPS-1)*16 + b)*Hsz + k];
}

/* ---------- transpose: dst[k][r] (dup: pairs (v,v) at [k][2r]) from src[r][k0..] ---------- */
__global__ void k_tr(const float* __restrict__ src, float* __restrict__ dst,
                     int R, int lds, int ldd, int dup){
    __shared__ float t[32][33];
    int k0 = blockIdx.x*32, r0 = blockIdx.y*32;
    int x = threadIdx.x, y = threadIdx.y;
    #pragma unroll
    for (int i = y; i < 32; i += 8){
        int r = r0 + i;
        t[i][x] = (r < R) ? src[(size_t)r*lds + k0 + x] : 0.f;
    }
    __syncthreads();
    #pragma unroll
    for (int i = y; i < 32; i += 8){
        int k = k0 + i;
        int r = r0 + x;
        float v = t[x][i];
        if (dup){
            *(float2*)(dst + (size_t)k*ldd + 2*r) = make_float2(v, v);
        } else if (r < R){
            dst[(size_t)k*ldd + r] = v;
        }
    }
}

/* ---------- GEMM: C[M,N] = A@B^T + bias, via A2 (dup-transposed) and BT ----------
   cp.async 3-stage pipeline; FFMA2 with natural pairs (no pk2). */
#define AS_STRIDE 264
#define BS_STRIDE 136
#define GEMM_SMEM (3*(16*AS_STRIDE + 16*BS_STRIDE)*4)

template<bool SCATTER>
__global__ void __launch_bounds__(256, 2)
k_gemm(const float* __restrict__ A2, const float* __restrict__ BT,
       const float* __restrict__ bias, float* __restrict__ C,
       int M, int ldbt, int ldc)
{
    extern __shared__ float sm[];
    float* AsF = sm;
    float* BsF = sm + 3*16*AS_STRIDE;
    int tid = threadIdx.x;
    int tx = tid & 15, ty = tid >> 4;
    int m0 = blockIdx.x*128, n0 = blockIdx.y*128;
    const float* Ab = A2 + (size_t)m0*2;
    const float* Bb = BT + n0;
    unsigned sAs = (unsigned)__cvta_generic_to_shared(AsF);
    unsigned sBs = (unsigned)__cvta_generic_to_shared(BsF);

    ull acc[8][4];
    #pragma unroll
    for (int i = 0; i < 8; i++){
        #pragma unroll
        for (int j = 0; j < 4; j++) acc[i][j] = 0ull;
    }

    #define ISSUE(kt) do{                                                        \
        int _buf = (kt) % 3;                                                     \
        int _k0 = (kt)*16;                                                       \
        unsigned _sa = sAs + _buf*(16*AS_STRIDE*4);                              \
        unsigned _sb = sBs + _buf*(16*BS_STRIDE*4);                              \
        _Pragma("unroll")                                                        \
        for (int _i = 0; _i < 4; _i++){                                          \
            int _c = tid + _i*256;                                               \
            int _k = _c >> 6, _off = (_c & 63)*4;                                \
            asm volatile("cp.async.cg.shared.global [%0], [%1], 16;\n"           \
                :: "r"(_sa + (unsigned)(_k*AS_STRIDE + _off)*4),                 \
                   "l"(Ab + (size_t)(_k0+_k)*4096 + _off));                      \
        }                                                                        \
        _Pragma("unroll")                                                        \
        for (int _i = 0; _i < 2; _i++){                                          \
            int _c = tid + _i*256;                                               \
            int _k = _c >> 5, _off = (_c & 31)*4;                                \
            asm volatile("cp.async.cg.shared.global [%0], [%1], 16;\n"           \
                :: "r"(_sb + (unsigned)(_k*BS_STRIDE + _off)*4),                 \
                   "l"(Bb + (size_t)(_k0+_k)*ldbt + _off));                      \
        }                                                                        \
        asm volatile("cp.async.commit_group;\n");                                \
    } while(0)

    ISSUE(0);
    ISSUE(1);

    for (int t = 0; t < 32; t++){
        if (t < 31) asm volatile("cp.async.wait_group 1;\n" ::: "memory");
        else        asm volatile("cp.async.wait_group 0;\n" ::: "memory");
        __syncthreads();
        if (t < 30) ISSUE(t+2);
        const float* as = AsF + (t%3)*(16*AS_STRIDE) + ty*16;
        const float* bs = BsF + (t%3)*(16*BS_STRIDE) + tx*8;
        #pragma unroll
        for (int kk = 0; kk < 16; kk++){
            ulonglong2 a01 = *(const ulonglong2*)(as + kk*AS_STRIDE);
            ulonglong2 a23 = *(const ulonglong2*)(as + kk*AS_STRIDE + 4);
            ulonglong2 a45 = *(const ulonglong2*)(as + kk*AS_STRIDE + 8);
            ulonglong2 a67 = *(const ulonglong2*)(as + kk*AS_STRIDE + 12);
            ulonglong2 b01 = *(const ulonglong2*)(bs + kk*BS_STRIDE);
            ulonglong2 b23 = *(const ulonglong2*)(bs + kk*BS_STRIDE + 4);
            ull ap[8] = {a01.x, a01.y, a23.x, a23.y, a45.x, a45.y, a67.x, a67.y};
            #pragma unroll
            for (int i = 0; i < 8; i++){
                fma2(acc[i][0], ap[i], b01.x);
                fma2(acc[i][1], ap[i], b01.y);
                fma2(acc[i][2], ap[i], b23.x);
                fma2(acc[i][3], ap[i], b23.y);
            }
        }
    }
    #undef ISSUE

    float bb[8];
    #pragma unroll
    for (int c = 0; c < 8; c++) bb[c] = __ldg(bias + n0 + tx*8 + c);

    #pragma unroll
    for (int i = 0; i < 8; i++){
        int row = m0 + ty*8 + i;
        if (row < M){
            float* dst;
            if (SCATTER){
                int b = row & 15, s = row >> 4;
                dst = C + (size_t)b*Tsz*Vsz + (size_t)(s+1)*Vsz + n0 + tx*8;
            } else {
                dst = C + (size_t)row*ldc + n0 + tx*8;
            }
            float4 r0, r1;
            upk2(acc[i][0], r0.x, r0.y); upk2(acc[i][1], r0.z, r0.w);
            upk2(acc[i][2], r1.x, r1.y); upk2(acc[i][3], r1.z, r1.w);
            r0.x += bb[0]; r0.y += bb[1]; r0.z += bb[2]; r0.w += bb[3];
            r1.x += bb[4]; r1.y += bb[5]; r1.z += bb[6]; r1.w += bb[7];
            *(float4*)dst = r0; *(float4*)(dst+4) = r1;
        }
    }
}

/* ---------- persistent recurrence ---------- */
__device__ __forceinline__ void gbar(int p){
    __syncthreads();
    if (threadIdx.x < 32){
        if (threadIdx.x == 0){ __threadfence(); g_flags[blockIdx.x] = p; }
        __syncwarp();
        int i0 = threadIdx.x*4;
        for (;;){
            int a = g_flags[i0], b = g_flags[i0+1];
            int c = g_flags[i0+2], d = g_flags[i0+3];
            int mn = min(min(a,b), min(c,d));
            if (__all_sync(0xffffffffu, mn >= p)) break;
        }
        if (threadIdx.x == 0) __threadfence();
    }
    __syncthreads();
}

#define SHP 18
__device__ __forceinline__ void stageSH(float* SH, const float* src){
    __syncthreads();
    for (int i = threadIdx.x; i < Hsz*Bsz; i += 256)
        SH[(i>>4)*SHP + (i&15)] = __ldcg(src + i);
    __syncthreads();
}

/* warp: 2 rows x 16 batches (as 8 pairs), K=512; SH = rhs [k][b] pad SHP */
__device__ __forceinline__ void bgemm2p(const float* __restrict__ w0r, const float* __restrict__ w1r,
                                        float bias0, float bias1,
                                        float* o0, float* o1, int st,
                                        const float* SH, int lane)
{
    ull ap0[8], ap1[8];
    #pragma unroll
    for (int j = 0; j < 8; j++){ ap0[j] = 0ull; ap1[j] = 0ull; }
    #pragma unroll 8
    for (int ki = 0; ki < 16; ki++){
        int k = ki*32 + lane;
        float w0 = __ldg(w0r + k), w1 = __ldg(w1r + k);
        ull wp0 = pk2(w0, w0), wp1 = pk2(w1, w1);
        const ull* hv = (const ull*)(SH + k*SHP);
        #pragma unroll
        for (int j = 0; j < 8; j++){
            ull h2 = hv[j];
            fma2(ap0[j], wp0, h2);
            fma2(ap1[j], wp1, h2);
        }
    }
    #pragma unroll
    for (int j = 0; j < 8; j++){ ap0[j] = wred64(ap0[j]); ap1[j] = wred64(ap1[j]); }
    if (lane < 8){
        float lo, hi; upk2(ap0[lane], lo, hi);
        __stcg(o0 + (2*lane)*st,   lo + bias0);
        __stcg(o0 + (2*lane+1)*st, hi + bias0);
    } else if (lane < 16){
        int j = lane - 8;
        float lo, hi; upk2(ap1[j], lo, hi);
        __stcg(o1 + (2*j)*st,   lo + bias1);
        __stcg(o1 + (2*j+1)*st, hi + bias1);
    }
}

__global__ void __launch_bounds__(256)
k_recur(const float* __restrict__ enc, const int* __restrict__ mask,
        const float* __restrict__ Wq,  const float* __restrict__ bq,
        const float* __restrict__ Whh, const float* __restrict__ bhh,
        const float* __restrict__ Wih, const float* __restrict__ Wc,
        const float* __restrict__ bc)
{
    __shared__ float SH[Hsz*SHP];
    int tid = threadIdx.x;
    int lane = tid & 31;
    int wg = blockIdx.x*8 + (tid >> 5);        /* 0..1023 */
    float bcv = __ldg(bc);
    int p = 0;

    for (int s = 0; s < STEPS; s++){
        /* ---- phase A: q = h@Wq^T+bq ; gh = h@Whh^T+bhh (f32x2 pairs) ---- */
        stageSH(SH, g_hT + (s&1)*(Hsz*Bsz));
        {
            int r0 = 2*wg;
            if (r0 < 512){
                bgemm2p(Wq + (size_t)r0*512, Wq + (size_t)(r0+1)*512,
                        __ldg(bq+r0), __ldg(bq+r0+1),
                        g_q + r0, g_q + r0 + 1, 512, SH, lane);
            } else {
                int g = r0 - 512;
                bgemm2p(Whh + (size_t)g*512, Whh + (size_t)(g+1)*512,
                        __ldg(bhh+g), __ldg(bhh+g+1),
                        g_gh + g, g_gh + g + 1, 1536, SH, lane);
            }
        }
        gbar(++p);

        /* ---- phase B: scores ---- */
        {
            int pr0 = 2*wg;
            int b = pr0 >> 7, t0 = pr0 & 127;
            const float* qp = g_q + b*Hsz;
            float qk[16], wv[16];
            #pragma unroll
            for (int ki = 0; ki < 16; ki++){
                int k = ki*32 + lane;
                qk[ki] = __ldcg(qp + k);
                wv[ki] = __ldg(Wc + k);
            }
            #pragma unroll
            for (int i = 0; i < 2; i++){
                int t = t0 + i;
                const float* vp = g_vt + ((size_t)b*Tsz + t)*Hsz;
                float vv[16];
                #pragma unroll
                for (int ki = 0; ki < 16; ki++) vv[ki] = __ldg(vp + ki*32 + lane);
                float acc = 0.f;
                #pragma unroll
                for (int ki = 0; ki < 16; ki++) acc += wv[ki] * ftanh(qk[ki] + vv[ki]);
                acc = wred(acc);
                if (lane == 0){
                    float sc = acc + bcv;
                    if (__ldg(mask + b*Tsz + t) == 0) sc = -FLT_MAX;
                    __stcg(g_scores + b*Tsz + t, sc);
                }
            }
        }
        gbar(++p);

        /* ---- phase C: softmax + ctx (CTA = (b, 64-dim chunk)) ---- */
        {
            int b = blockIdx.x >> 3, ch = blockIdx.x & 7, hb = ch*64;
            __syncthreads();
            float sv = -FLT_MAX;
            if (tid < 128){
                sv = __ldcg(g_scores + b*Tsz + tid);
                float m = wmax(sv);
                if (lane == 0) SH[640 + (tid>>5)] = m;
            }
            __syncthreads();
            if (tid == 0)
                SH[648] = fmaxf(fmaxf(SH[640],SH[641]), fmaxf(SH[642],SH[643]));
            __syncthreads();
            if (tid < 128){
                float e = __expf(sv - SH[648]);
                SH[tid] = e;
                float sm = wred(e);
                if (lane == 0) SH[652 + (tid>>5)] = sm;
            }
            __syncthreads();
            if (tid == 0)
                SH[649] = __fdividef(1.f, SH[652]+SH[653]+SH[654]+SH[655]);
            __syncthreads();
            float inv = SH[649];
            int d = tid & 63, tq = tid >> 6;
            const float* ep = enc + ((size_t)b*Tsz + tq*32)*Hsz + hb + d;
            float part = 0.f;
            #pragma unroll 8
            for (int i = 0; i < 32; i++)
                part += SH[tq*32 + i] * __ldg(ep + (size_t)i*Hsz);
            SH[768 + tq*64 + d] = part;
            __syncthreads();
            if (tid < 64){
                float v = (SH[768+tid] + SH[832+tid] + SH[896+tid] + SH[960+tid]) * inv;
                __stcg(g_ctxT + (hb + tid)*16 + b, v);
            }
        }
        gbar(++p);

        /* ---- phase D: gic + GRU update (f32x2 pairs) ---- */
        stageSH(SH, g_ctxT);
        {
            int j = wg >> 1, bh = (wg & 1)*8;
            ull ar[4], az[4], an[4];
            #pragma unroll
            for (int q = 0; q < 4; q++){ ar[q]=0ull; az[q]=0ull; an[q]=0ull; }
            const float* wr = Wih + (size_t)j*1024 + 512;
            const float* wz = Wih + (size_t)(j+512)*1024 + 512;
            const float* wn = Wih + (size_t)(j+1024)*1024 + 512;
            #pragma unroll 8
            for (int ki = 0; ki < 16; ki++){
                int k = ki*32 + lane;
                float r_ = __ldg(wr + k), z_ = __ldg(wz + k), n_ = __ldg(wn + k);
                ull rp = pk2(r_, r_), zp = pk2(z_, z_), np = pk2(n_, n_);
                const ull* hv = (const ull*)(SH + k*SHP + bh);
                #pragma unroll
                for (int q = 0; q < 4; q++){
                    ull c2 = hv[q];
                    fma2(ar[q], rp, c2);
                    fma2(az[q], zp, c2);
                    fma2(an[q], np, c2);
                }
            }
            #pragma unroll
            for (int q = 0; q < 4; q++){
                ar[q] = wred64(ar[q]); az[q] = wred64(az[q]); an[q] = wred64(an[q]);
            }
            if (lane < 4){
                float vr0, vr1, vz0, vz1, vn0, vn1;
                upk2(ar[lane], vr0, vr1);
                upk2(az[lane], vz0, vz1);
                upk2(an[lane], vn0, vn1);
                #pragma unroll
                for (int h = 0; h < 2; h++){
                    int bb = bh + 2*lane + h;
                    float v0 = h ? vr1 : vr0;
                    float v1 = h ? vz1 : vz0;
                    float v2 = h ? vn1 : vn0;
                    size_t m = (size_t)s*16 + bb;
                    float gir = __ldg(g_gix + m*1536 + j)        + v0;
                    float giz = __ldg(g_gix + m*1536 + 512 + j)  + v1;
                    float gin = __ldg(g_gix + m*1536 + 1024 + j) + v2;
                    float ghr = __ldcg(g_gh + bb*1536 + j);
                    float ghz = __ldcg(g_gh + bb*1536 + 512 + j);
                    float ghn = __ldcg(g_gh + bb*1536 + 1024 + j);
                    float hp  = __ldcg(g_hT + (s&1)*(Hsz*Bsz) + j*16 + bb);
                    float rr = fsig(gir + ghr);
                    float zz = fsig(giz + ghz);
                    float nn = ftanh(gin + rr*ghn);
                    float hN = (1.0f - zz)*nn + zz*hp;
                    __stcg(g_Hs + m*Hsz + j, hN);
                    __stcg(g_hT + ((s+1)&1)*(Hsz*Bsz) + j*16 + bb, hN);
                }
            }
        }
        gbar(++p);
    }
}

/* ---------- launch ---------- */
extern "C" void kernel_launch(void* const* d_in, const int* in_sizes, int n_in,
                              void* d_out, int out_size)
{
    const float* enc  = (const float*)d_in[0];
    const float* eh   = (const float*)d_in[1];
    const int*   msk  = (const int*)  d_in[2];
    const int*   tgt  = (const int*)  d_in[3];
    const float* emb  = (const float*)d_in[4];
    const float* Wq   = (const float*)d_in[5];
    const float* bq   = (const float*)d_in[6];
    const float* Wv   = (const float*)d_in[7];
    const float* bv   = (const float*)d_in[8];
    const float* Wc   = (const float*)d_in[9];
    const float* bc   = (const float*)d_in[10];
    const float* Wih  = (const float*)d_in[11];
    const float* Whh  = (const float*)d_in[12];
    const float* bih  = (const float*)d_in[13];
    const float* bhh  = (const float*)d_in[14];
    const float* Wo   = (const float*)d_in[15];
    const float* bo   = (const float*)d_in[16];
    float* out = (float*)d_out;

    float *p_vt, *p_xe, *p_gix, *p_Hs, *p_a2, *p_bt;
    cudaGetSymbolAddress((void**)&p_vt,  g_vt);
    cudaGetSymbolAddress((void**)&p_xe,  g_xe);
    cudaGetSymbolAddress((void**)&p_gix, g_gix);
    cudaGetSymbolAddress((void**)&p_Hs,  g_Hs);
    cudaGetSymbolAddress((void**)&p_a2,  g_a2);
    cudaGetSymbolAddress((void**)&p_bt,  g_bt);

    cudaFuncSetAttribute(k_gemm<false>, cudaFuncAttributeMaxDynamicSharedMemorySize, GEMM_SMEM);
    cudaFuncSetAttribute(k_gemm<true>,  cudaFuncAttributeMaxDynamicSharedMemorySize, GEMM_SMEM);

    dim3 trb(32, 8);
    k_h0<<<32, 256>>>(eh);
    k_gather<<<MR, 256>>>(emb, tgt);

    /* vt = enc @ Wv^T + bv */
    k_tr<<<dim3(16,16),  trb>>>(Wv,  p_bt, 512, 512, 512, 0);
    k_tr<<<dim3(16,64),  trb>>>(enc, p_a2, 2048, 512, 4096, 1);
    k_gemm<false><<<dim3(16,4), 256, GEMM_SMEM>>>(p_a2, p_bt, bv, p_vt, Bsz*Tsz, 512, 512);

    /* gix = xe @ Wih[:, :H]^T + bih */
    k_tr<<<dim3(16,48),  trb>>>(Wih, p_bt, 1536, 1024, 1536, 0);
    k_tr<<<dim3(16,64),  trb>>>(p_xe, p_a2, MR, 512, 4096, 1);
    k_gemm<false><<<dim3(16,12), 256, GEMM_SMEM>>>(p_a2, p_bt, bih, p_gix, MR, 1536, 1536);

    k_zero<<<2000, 256>>>(out);
    k_recur<<<NB, 256>>>(enc, msk, Wq, bq, Whh, bhh, Wih, Wc, bc);

    /* logits = Hs @ Wo^T + bo, scattered into out[b, s+1, :] */
    k_tr<<<dim3(16,1000), trb>>>(Wo, p_bt, Vsz, 512, Vsz, 0);
    k_tr<<<dim3(16,64),   trb>>>(p_Hs, p_a2, MR, 512, 4096, 1);
    k_gemm<true><<<dim3(16,250), 256, GEMM_SMEM>>>(p_a2, p_bt, bo, out, MR, Vsz, 0);

    if (out_size >= Bsz*Tsz*Vsz + Bsz*Hsz)
        k_tail<<<32, 256>>>(out);
}

// round 13
// speedup vs baseline: 1.0082x; 1.0082x over previous
#include <cuda_runtime.h>
#include <math.h>
#include <float.h>

#define Bsz 16
#define Tsz 128
#define Hsz 512
#define Vsz 32000
#define STEPS 127
#define MR (STEPS*Bsz)   /* 2032 */
#define NB 128

/* ---------- device scratch ---------- */
__device__ float g_vt[Bsz*Tsz*Hsz];
__device__ float g_xe[MR*Hsz];
__device__ float g_gix[MR*3*Hsz];
__device__ float g_Hs[MR*Hsz];
__device__ float g_q[Bsz*Hsz];
__device__ float g_gh[Bsz*3*Hsz];
__device__ float g_scores[Bsz*Tsz];
__device__ float g_ctxT[Hsz*Bsz];
__device__ float g_hT[2*Hsz*Bsz];
__device__ volatile int g_flags[NB];

/* ---------- helpers ---------- */
typedef unsigned long long ull;
__device__ __forceinline__ ull pk2(float lo, float hi){
    ull r; asm("mov.b64 %0,{%1,%2};" : "=l"(r) : "f"(lo), "f"(hi)); return r;
}
__device__ __forceinline__ void upk2(ull v, float& lo, float& hi){
    asm("mov.b64 {%0,%1},%2;" : "=f"(lo), "=f"(hi) : "l"(v));
}
__device__ __forceinline__ void fma2(ull& d, ull a, ull b){
    asm("fma.rn.f32x2 %0,%1,%2,%0;" : "+l"(d) : "l"(a), "l"(b));
}
__device__ __forceinline__ ull addp(ull a, ull b){
    ull r; asm("add.rn.f32x2 %0,%1,%2;" : "=l"(r) : "l"(a), "l"(b)); return r;
}
__device__ __forceinline__ ull wred64(ull v){
    #pragma unroll
    for (int o = 16; o > 0; o >>= 1)
        v = addp(v, __shfl_xor_sync(0xffffffffu, v, o));
    return v;
}
__device__ __forceinline__ float wred(float v){
    #pragma unroll
    for (int o = 16; o > 0; o >>= 1) v += __shfl_xor_sync(0xffffffffu, v, o);
    return v;
}
__device__ __forceinline__ float wmax(float v){
    #pragma unroll
    for (int o = 16; o > 0; o >>= 1) v = fmaxf(v, __shfl_xor_sync(0xffffffffu, v, o));
    return v;
}
__device__ __forceinline__ float ftanh(float x){
    float cx = fminf(fmaxf(x, -9.f), 9.f);
    float e = __expf(2.f*cx);
    return __fdividef(e - 1.f, e + 1.f);
}
__device__ __forceinline__ float fsig(float x){
    float cx = fminf(fmaxf(x, -30.f), 30.f);
    return __fdividef(1.f, 1.f + __expf(-cx));
}

/* ---------- init ---------- */
__global__ void k_h0(const float* __restrict__ eh){
    int i = blockIdx.x*256 + threadIdx.x;
    if (i < Hsz*Bsz){
        int b = i >> 9, k = i & 511;
        g_hT[k*16 + b] = eh[i];
    }
    if (blockIdx.x == 0 && threadIdx.x < NB) g_flags[threadIdx.x] = 0;
}

__global__ void k_gather(const float* __restrict__ emb, const int* __restrict__ tgt){
    int m = blockIdx.x;
    int s = m >> 4, b = m & 15;
    int tok = (s == 0) ? 1 : tgt[b*Tsz + s];
    const float4* src = (const float4*)(emb + (size_t)tok*Hsz);
    float4* dst = (float4*)(g_xe + (size_t)m*Hsz);
    for (int i = threadIdx.x; i < Hsz/4; i += blockDim.x) dst[i] = src[i];
}

__global__ void k_zero(float* __restrict__ out){
    int i = blockIdx.x*256 + threadIdx.x;
    int b = i / Vsz, v = i - b*Vsz;
    out[(size_t)b*Tsz*Vsz + v] = 0.0f;
}

__global__ void k_tail(float* __restrict__ out){
    int i = blockIdx.x*256 + threadIdx.x;
    int b = i >> 9, k = i & 511;
    out[(size_t)Bsz*Tsz*Vsz + i] = g_Hs[(size_t)((STEPS-1)*16 + b)*Hsz + k];
}

/* ---------- GEMM: C[M,N] = A @ B^T + bias.  A[M,512], B[N,ldb] row-major.
   512 threads, 128x128 tile, thread = 4 M-pairs x 4 N, FFMA2, double-buffered. */
template<bool SCATTER>
__global__ void __launch_bounds__(512)
k_gemm(const float* __restrict__ A, const float* __restrict__ B,
       const float* __restrict__ bias, float* __restrict__ C,
       int M, int ldb, int ldc)
{
    __shared__ __align__(16) float As[2][16][132];
    __shared__ __align__(16) float Bs[2][16][132];
    int tid = threadIdx.x;
    int tx = tid & 31, ty = tid >> 5;          /* tx: N/4 slot, ty: M/8 slot */
    int m0 = blockIdx.x*128, n0 = blockIdx.y*128;
    int lm = tid >> 2, lkq = (tid & 3)*4;      /* staging: row 0..127, k quad */

    ull acc[4][4];
    #pragma unroll
    for (int i = 0; i < 4; i++){
        #pragma unroll
        for (int j = 0; j < 4; j++) acc[i][j] = 0ull;
    }

    bool av = (m0 + lm) < M;
    const float* Arow = A + (size_t)(m0 + lm)*512 + lkq;
    const float* Brow = B + (size_t)(n0 + lm)*ldb + lkq;

    /* prologue: tile 0 */
    {
        float4 a = av ? *(const float4*)(Arow) : make_float4(0,0,0,0);
        float4 b = *(const float4*)(Brow);
        As[0][lkq+0][lm]=a.x; As[0][lkq+1][lm]=a.y; As[0][lkq+2][lm]=a.z; As[0][lkq+3][lm]=a.w;
        Bs[0][lkq+0][lm]=b.x; Bs[0][lkq+1][lm]=b.y; Bs[0][lkq+2][lm]=b.z; Bs[0][lkq+3][lm]=b.w;
    }
    __syncthreads();

    int cur = 0;
    for (int t = 0; t < 32; t++){
        float4 na, nb;
        if (t < 31){
            int k0 = (t+1)*16;
            na = av ? *(const float4*)(Arow + k0) : make_float4(0,0,0,0);
            nb = *(const float4*)(Brow + k0);
        }
        const float* as = &As[cur][0][ty*8];
        const float* bs = &Bs[cur][0][tx*4];
        #pragma unroll
        for (int kk = 0; kk < 16; kk++){
            ulonglong2 ap = *(const ulonglong2*)(as + kk*132);       /* m pairs 0,1 */
            ulonglong2 aq = *(const ulonglong2*)(as + kk*132 + 4);   /* m pairs 2,3 */
            float4 bf = *(const float4*)(bs + kk*132);
            ull b0 = pk2(bf.x, bf.x), b1 = pk2(bf.y, bf.y);
            ull b2 = pk2(bf.z, bf.z), b3 = pk2(bf.w, bf.w);
            fma2(acc[0][0], ap.x, b0); fma2(acc[0][1], ap.x, b1);
            fma2(acc[0][2], ap.x, b2); fma2(acc[0][3], ap.x, b3);
            fma2(acc[1][0], ap.y, b0); fma2(acc[1][1], ap.y, b1);
            fma2(acc[1][2], ap.y, b2); fma2(acc[1][3], ap.y, b3);
            fma2(acc[2][0], aq.x, b0); fma2(acc[2][1], aq.x, b1);
            fma2(acc[2][2], aq.x, b2); fma2(acc[2][3], aq.x, b3);
            fma2(acc[3][0], aq.y, b0); fma2(acc[3][1], aq.y, b1);
            fma2(acc[3][2], aq.y, b2); fma2(acc[3][3], aq.y, b3);
        }
        if (t < 31){
            int nx = cur ^ 1;
            As[nx][lkq+0][lm]=na.x; As[nx][lkq+1][lm]=na.y; As[nx][lkq+2][lm]=na.z; As[nx][lkq+3][lm]=na.w;
            Bs[nx][lkq+0][lm]=nb.x; Bs[nx][lkq+1][lm]=nb.y; Bs[nx][lkq+2][lm]=nb.z; Bs[nx][lkq+3][lm]=nb.w;
        }
        __syncthreads();
        cur ^= 1;
    }

    float bb[4];
    #pragma unroll
    for (int c = 0; c < 4; c++) bb[c] = __ldg(bias + n0 + tx*4 + c);

    #pragma unroll
    for (int mp = 0; mp < 4; mp++){
        float4 r0, r1;
        upk2(acc[mp][0], r0.x, r1.x);
        upk2(acc[mp][1], r0.y, r1.y);
        upk2(acc[mp][2], r0.z, r1.z);
        upk2(acc[mp][3], r0.w, r1.w);
        r0.x += bb[0]; r0.y += bb[1]; r0.z += bb[2]; r0.w += bb[3];
        r1.x += bb[0]; r1.y += bb[1]; r1.z += bb[2]; r1.w += bb[3];
        #pragma unroll
        for (int h = 0; h < 2; h++){
            int row = m0 + ty*8 + 2*mp + h;
            if (row < M){
                float* dst;
                if (SCATTER){
                    int b = row & 15, s = row >> 4;
                    dst = C + (size_t)b*Tsz*Vsz + (size_t)(s+1)*Vsz + n0 + tx*4;
                } else {
                    dst = C + (size_t)row*ldc + n0 + tx*4;
                }
                *(float4*)dst = h ? r1 : r0;
            }
        }
    }
}

/* ---------- persistent recurrence (PROVEN barrier: volatile flat poll) ---------- */
__device__ __forceinline__ void gbar(int p){
    __syncthreads();
    if (threadIdx.x < 32){
        if (threadIdx.x == 0){ __threadfence(); g_flags[blockIdx.x] = p; }
        __syncwarp();
        int i0 = threadIdx.x*4;
        for (;;){
            int a = g_flags[i0], b = g_flags[i0+1];
            int c = g_flags[i0+2], d = g_flags[i0+3];
            int mn = min(min(a,b), min(c,d));
            if (__all_sync(0xffffffffu, mn >= p)) break;
        }
        if (threadIdx.x == 0) __threadfence();
    }
    __syncthreads();
}

#define SHP 18
__device__ __forceinline__ void stageSH(float* SH, const float* src){
    __syncthreads();
    for (int i = threadIdx.x; i < Hsz*Bsz; i += 256)
        SH[(i>>4)*SHP + (i&15)] = __ldcg(src + i);
    __syncthreads();
}

/* warp: 2 rows x 16 batches (as 8 pairs), K=512; SH = rhs [k][b] pad SHP */
__device__ __forceinline__ void bgemm2p(const float* __restrict__ w0r, const float* __restrict__ w1r,
                                        float bias0, float bias1,
                                        float* o0, float* o1, int st,
                                        const float* SH, int lane)
{
    ull ap0[8], ap1[8];
    #pragma unroll
    for (int j = 0; j < 8; j++){ ap0[j] = 0ull; ap1[j] = 0ull; }
    #pragma unroll 8
    for (int ki = 0; ki < 16; ki++){
        int k = ki*32 + lane;
        float w0 = __ldg(w0r + k), w1 = __ldg(w1r + k);
        ull wp0 = pk2(w0, w0), wp1 = pk2(w1, w1);
        const ull* hv = (const ull*)(SH + k*SHP);
        #pragma unroll
        for (int j = 0; j < 8; j++){
            ull h2 = hv[j];
            fma2(ap0[j], wp0, h2);
            fma2(ap1[j], wp1, h2);
        }
    }
    #pragma unroll
    for (int j = 0; j < 8; j++){ ap0[j] = wred64(ap0[j]); ap1[j] = wred64(ap1[j]); }
    if (lane < 8){
        float lo, hi; upk2(ap0[lane], lo, hi);
        __stcg(o0 + (2*lane)*st,   lo + bias0);
        __stcg(o0 + (2*lane+1)*st, hi + bias0);
    } else if (lane < 16){
        int j = lane - 8;
        float lo, hi; upk2(ap1[j], lo, hi);
        __stcg(o1 + (2*j)*st,   lo + bias1);
        __stcg(o1 + (2*j+1)*st, hi + bias1);
    }
}

__global__ void __launch_bounds__(256)
k_recur(const float* __restrict__ enc, const int* __restrict__ mask,
        const float* __restrict__ Wq,  const float* __restrict__ bq,
        const float* __restrict__ Whh, const float* __restrict__ bhh,
        const float* __restrict__ Wih, const float* __restrict__ Wc,
        const float* __restrict__ bc)
{
    __shared__ __align__(16) float SH[Hsz*SHP];
    int tid = threadIdx.x;
    int lane = tid & 31;
    int wg = blockIdx.x*8 + (tid >> 5);        /* 0..1023 */
    float bcv = __ldg(bc);
    int p = 0;

    for (int s = 0; s < STEPS; s++){
        /* ---- phase A: q = h@Wq^T+bq ; gh = h@Whh^T+bhh (f32x2 pairs) ---- */
        stageSH(SH, g_hT + (s&1)*(Hsz*Bsz));
        {
            int r0 = 2*wg;
            if (r0 < 512){
                bgemm2p(Wq + (size_t)r0*512, Wq + (size_t)(r0+1)*512,
                        __ldg(bq+r0), __ldg(bq+r0+1),
                        g_q + r0, g_q + r0 + 1, 512, SH, lane);
            } else {
                int g = r0 - 512;
                bgemm2p(Whh + (size_t)g*512, Whh + (size_t)(g+1)*512,
                        __ldg(bhh+g), __ldg(bhh+g+1),
                        g_gh + g, g_gh + g + 1, 1536, SH, lane);
            }
        }
        gbar(++p);

        /* ---- phase B: scores ---- */
        {
            int pr0 = 2*wg;
            int b = pr0 >> 7, t0 = pr0 & 127;
            const float* qp = g_q + b*Hsz;
            float qk[16], wv[16];
            #pragma unroll
            for (int ki = 0; ki < 16; ki++){
                int k = ki*32 + lane;
                qk[ki] = __ldcg(qp + k);
                wv[ki] = __ldg(Wc + k);
            }
            #pragma unroll
            for (int i = 0; i < 2; i++){
                int t = t0 + i;
                const float* vp = g_vt + ((size_t)b*Tsz + t)*Hsz;
                float vv[16];
                #pragma unroll
                for (int ki = 0; ki < 16; ki++) vv[ki] = __ldg(vp + ki*32 + lane);
                float acc = 0.f;
                #pragma unroll
                for (int ki = 0; ki < 16; ki++) acc += wv[ki] * ftanh(qk[ki] + vv[ki]);
                acc = wred(acc);
                if (lane == 0){
                    float sc = acc + bcv;
                    if (__ldg(mask + b*Tsz + t) == 0) sc = -FLT_MAX;
                    __stcg(g_scores + b*Tsz + t, sc);
                }
            }
        }
        gbar(++p);

        /* ---- phase C: softmax + ctx (CTA = (b, 64-dim chunk)) ---- */
        {
            int b = blockIdx.x >> 3, ch = blockIdx.x & 7, hb = ch*64;
            __syncthreads();
            float sv = -FLT_MAX;
            if (tid < 128){
                sv = __ldcg(g_scores + b*Tsz + tid);
                float m = wmax(sv);
                if (lane == 0) SH[640 + (tid>>5)] = m;
            }
            __syncthreads();
            if (tid == 0)
                SH[648] = fmaxf(fmaxf(SH[640],SH[641]), fmaxf(SH[642],SH[643]));
            __syncthreads();
            if (tid < 128){
                float e = __expf(sv - SH[648]);
                SH[tid] = e;
                float sm = wred(e);
                if (lane == 0) SH[652 + (tid>>5)] = sm;
            }
            __syncthreads();
            if (tid == 0)
                SH[649] = __fdividef(1.f, SH[652]+SH[653]+SH[654]+SH[655]);
            __syncthreads();
            float inv = SH[649];
            int d = tid & 63, tq = tid >> 6;
            const float* ep = enc + ((size_t)b*Tsz + tq*32)*Hsz + hb + d;
            float part = 0.f;
            #pragma unroll 8
            for (int i = 0; i < 32; i++)
                part += SH[tq*32 + i] * __ldg(ep + (size_t)i*Hsz);
            SH[768 + tq*64 + d] = part;
            __syncthreads();
            if (tid < 64){
                float v = (SH[768+tid] + SH[832+tid] + SH[896+tid] + SH[960+tid]) * inv;
                __stcg(g_ctxT + (hb + tid)*16 + b, v);
            }
        }
        gbar(++p);

        /* ---- phase D: gic + GRU update (f32x2 pairs) ---- */
        stageSH(SH, g_ctxT);
        {
            int j = wg >> 1, bh = (wg & 1)*8;
            ull ar[4], az[4], an[4];
            #pragma unroll
            for (int q = 0; q < 4; q++){ ar[q]=0ull; az[q]=0ull; an[q]=0ull; }
            const float* wr = Wih + (size_t)j*1024 + 512;
            const float* wz = Wih + (size_t)(j+512)*1024 + 512;
            const float* wn = Wih + (size_t)(j+1024)*1024 + 512;
            #pragma unroll 8
            for (int ki = 0; ki < 16; ki++){
                int k = ki*32 + lane;
                float r_ = __ldg(wr + k), z_ = __ldg(wz + k), n_ = __ldg(wn + k);
                ull rp = pk2(r_, r_), zp = pk2(z_, z_), np = pk2(n_, n_);
                const ull* hv = (const ull*)(SH + k*SHP + bh);
                #pragma unroll
                for (int q = 0; q < 4; q++){
                    ull c2 = hv[q];
                    fma2(ar[q], rp, c2);
                    fma2(az[q], zp, c2);
                    fma2(an[q], np, c2);
                }
            }
            #pragma unroll
            for (int q = 0; q < 4; q++){
                ar[q] = wred64(ar[q]); az[q] = wred64(az[q]); an[q] = wred64(an[q]);
            }
            if (lane < 4){
                float vr0, vr1, vz0, vz1, vn0, vn1;
                upk2(ar[lane], vr0, vr1);
                upk2(az[lane], vz0, vz1);
                upk2(an[lane], vn0, vn1);
                #pragma unroll
                for (int h = 0; h < 2; h++){
                    int bb = bh + 2*lane + h;
                    float v0 = h ? vr1 : vr0;
                    float v1 = h ? vz1 : vz0;
                    float v2 = h ? vn1 : vn0;
                    size_t m = (size_t)s*16 + bb;
                    float gir = __ldg(g_gix + m*1536 + j)        + v0;
                    float giz = __ldg(g_gix + m*1536 + 512 + j)  + v1;
                    float gin = __ldg(g_gix + m*1536 + 1024 + j) + v2;
                    float ghr = __ldcg(g_gh + bb*1536 + j);
                    float ghz = __ldcg(g_gh + bb*1536 + 512 + j);
                    float ghn = __ldcg(g_gh + bb*1536 + 1024 + j);
                    float hp  = __ldcg(g_hT + (s&1)*(Hsz*Bsz) + j*16 + bb);
                    float rr = fsig(gir + ghr);
                    float zz = fsig(giz + ghz);
                    float nn = ftanh(gin + rr*ghn);
                    float hN = (1.0f - zz)*nn + zz*hp;
                    __stcg(g_Hs + m*Hsz + j, hN);
                    __stcg(g_hT + ((s+1)&1)*(Hsz*Bsz) + j*16 + bb, hN);
                }
            }
        }
        gbar(++p);
    }
}

/* ---------- launch ---------- */
extern "C" void kernel_launch(void* const* d_in, const int* in_sizes, int n_in,
                              void* d_out, int out_size)
{
    const float* enc  = (const float*)d_in[0];
    const float* eh   = (const float*)d_in[1];
    const int*   msk  = (const int*)  d_in[2];
    const int*   tgt  = (const int*)  d_in[3];
    const float* emb  = (const float*)d_in[4];
    const float* Wq   = (const float*)d_in[5];
    const float* bq   = (const float*)d_in[6];
    const float* Wv   = (const float*)d_in[7];
    const float* bv   = (const float*)d_in[8];
    const float* Wc   = (const float*)d_in[9];
    const float* bc   = (const float*)d_in[10];
    const float* Wih  = (const float*)d_in[11];
    const float* Whh  = (const float*)d_in[12];
    const float* bih  = (const float*)d_in[13];
    const float* bhh  = (const float*)d_in[14];
    const float* Wo   = (const float*)d_in[15];
    const float* bo   = (const float*)d_in[16];
    float* out = (float*)d_out;

    float *p_vt, *p_xe, *p_gix, *p_Hs;
    cudaGetSymbolAddress((void**)&p_vt,  g_vt);
    cudaGetSymbolAddress((void**)&p_xe,  g_xe);
    cudaGetSymbolAddress((void**)&p_gix, g_gix);
    cudaGetSymbolAddress((void**)&p_Hs,  g_Hs);

    k_h0<<<32, 256>>>(eh);
    k_gather<<<MR, 256>>>(emb, tgt);

    /* vt = enc @ Wv^T + bv : M=2048 N=512 */
    k_gemm<false><<<dim3(16,4), 512>>>(enc, Wv, bv, p_vt, Bsz*Tsz, 512, 512);
    /* gix = xe @ Wih[:, :H]^T + bih : M=2032 N=1536 (ldb = 2H = 1024) */
    k_gemm<false><<<dim3(16,12), 512>>>(p_xe, Wih, bih, p_gix, MR, 1024, 1536);

    k_zero<<<2000, 256>>>(out);
    k_recur<<<NB, 256>>>(enc, msk, Wq, bq, Whh, bhh, Wih, Wc, bc);

    /* logits = Hs @ Wo^T + bo, scattered into out[b, s+1, :] : M=2032 N=32000 */
    k_gemm<true><<<dim3(16,250), 512>>>(p_Hs, Wo, bo, out, MR, 512, 0);

    if (out_size >= Bsz*Tsz*Vsz + Bsz*Hsz)
        k_tail<<<32, 256>>>(out);
}

// round 14
// speedup vs baseline: 1.8146x; 1.7998x over previous
#include <cuda_runtime.h>
#include <math.h>
#include <float.h>

#define Bsz 16
#define Tsz 128
#define Hsz 512
#define Vsz 32000
#define STEPS 127
#define MR (STEPS*Bsz)   /* 2032 */
#define NB 64

/* ---------- device scratch ---------- */
__device__ float g_vt[Bsz*Tsz*Hsz];
__device__ float g_xe[MR*Hsz];
__device__ float g_gix[MR*3*Hsz];
__device__ float g_Hs[MR*Hsz];
__device__ float g_q[Bsz*Hsz];
__device__ float g_gh[Bsz*3*Hsz];
__device__ float g_scores[Bsz*Tsz];
__device__ float g_ctxT[Hsz*Bsz];
__device__ float g_hT[2*Hsz*Bsz];
__device__ volatile int g_flags[NB];
__device__ volatile int g_rel;

/* ---------- helpers ---------- */
typedef unsigned long long ull;
__device__ __forceinline__ ull pk2(float lo, float hi){
    ull r; asm("mov.b64 %0,{%1,%2};" : "=l"(r) : "f"(lo), "f"(hi)); return r;
}
__device__ __forceinline__ void upk2(ull v, float& lo, float& hi){
    asm("mov.b64 {%0,%1},%2;" : "=f"(lo), "=f"(hi) : "l"(v));
}
__device__ __forceinline__ void fma2(ull& d, ull a, ull b){
    asm("fma.rn.f32x2 %0,%1,%2,%0;" : "+l"(d) : "l"(a), "l"(b));
}
__device__ __forceinline__ ull addp(ull a, ull b){
    ull r; asm("add.rn.f32x2 %0,%1,%2;" : "=l"(r) : "l"(a), "l"(b)); return r;
}
__device__ __forceinline__ ull wred64(ull v){
    #pragma unroll
    for (int o = 16; o > 0; o >>= 1)
        v = addp(v, __shfl_xor_sync(0xffffffffu, v, o));
    return v;
}
__device__ __forceinline__ float wred(float v){
    #pragma unroll
    for (int o = 16; o > 0; o >>= 1) v += __shfl_xor_sync(0xffffffffu, v, o);
    return v;
}
__device__ __forceinline__ float wmax(float v){
    #pragma unroll
    for (int o = 16; o > 0; o >>= 1) v = fmaxf(v, __shfl_xor_sync(0xffffffffu, v, o));
    return v;
}
__device__ __forceinline__ float ftanh(float x){
    float cx = fminf(fmaxf(x, -9.f), 9.f);
    float e = __expf(2.f*cx);
    return __fdividef(e - 1.f, e + 1.f);
}
__device__ __forceinline__ float fsig(float x){
    float cx = fminf(fmaxf(x, -30.f), 30.f);
    return __fdividef(1.f, 1.f + __expf(-cx));
}

/* ---------- init ---------- */
__global__ void k_h0(const float* __restrict__ eh){
    int i = blockIdx.x*256 + threadIdx.x;
    if (i < Hsz*Bsz){
        int b = i >> 9, k = i & 511;
        g_hT[k*16 + b] = eh[i];
    }
    if (blockIdx.x == 0 && threadIdx.x < NB) g_flags[threadIdx.x] = 0;
    if (blockIdx.x == 0 && threadIdx.x == 0) g_rel = 0;
}

__global__ void k_gather(const float* __restrict__ emb, const int* __restrict__ tgt){
    int m = blockIdx.x;
    int s = m >> 4, b = m & 15;
    int tok = (s == 0) ? 1 : tgt[b*Tsz + s];
    const float4* src = (const float4*)(emb + (size_t)tok*Hsz);
    float4* dst = (float4*)(g_xe + (size_t)m*Hsz);
    for (int i = threadIdx.x; i < Hsz/4; i += blockDim.x) dst[i] = src[i];
}

__global__ void k_zero(float* __restrict__ out){
    int i = blockIdx.x*256 + threadIdx.x;
    int b = i / Vsz, v = i - b*Vsz;
    out[(size_t)b*Tsz*Vsz + v] = 0.0f;
}

__global__ void k_tail(float* __restrict__ out){
    int i = blockIdx.x*256 + threadIdx.x;
    int b = i >> 9, k = i & 511;
    out[(size_t)Bsz*Tsz*Vsz + i] = g_Hs[(size_t)((STEPS-1)*16 + b)*Hsz + k];
}

/* ---------- GEMM: C[M,N] = A @ B^T + bias.  A[M,512], B[N,ldb] row-major.
   256 threads, 128x128 tile, thread = 8 M-pairs x 4 N, FFMA2, double-buffered. */
template<bool SCATTER>
__global__ void __launch_bounds__(256, 2)
k_gemm(const float* __restrict__ A, const float* __restrict__ B,
       const float* __restrict__ bias, float* __restrict__ C,
       int M, int ldb, int ldc)
{
    __shared__ __align__(16) float As[2][16][132];
    __shared__ __align__(16) float Bs[2][16][132];
    int tid = threadIdx.x;
    int tx = tid & 31, ty = tid >> 5;          /* tx: N/4 slot (32), ty: M/16 slot (8) */
    int m0 = blockIdx.x*128, n0 = blockIdx.y*128;
    int lm = tid >> 1, lkq = (tid & 1)*8;      /* staging: row 0..127, 8-float k chunk */

    ull acc[8][4];
    #pragma unroll
    for (int i = 0; i < 8; i++){
        #pragma unroll
        for (int j = 0; j < 4; j++) acc[i][j] = 0ull;
    }

    bool av = (m0 + lm) < M;
    const float* Arow = A + (size_t)(m0 + lm)*512 + lkq;
    const float* Brow = B + (size_t)(n0 + lm)*ldb + lkq;

    /* prologue: tile 0 */
    {
        float4 a0 = av ? *(const float4*)(Arow)     : make_float4(0,0,0,0);
        float4 a1 = av ? *(const float4*)(Arow + 4) : make_float4(0,0,0,0);
        float4 b0 = *(const float4*)(Brow);
        float4 b1 = *(const float4*)(Brow + 4);
        As[0][lkq+0][lm]=a0.x; As[0][lkq+1][lm]=a0.y; As[0][lkq+2][lm]=a0.z; As[0][lkq+3][lm]=a0.w;
        As[0][lkq+4][lm]=a1.x; As[0][lkq+5][lm]=a1.y; As[0][lkq+6][lm]=a1.z; As[0][lkq+7][lm]=a1.w;
        Bs[0][lkq+0][lm]=b0.x; Bs[0][lkq+1][lm]=b0.y; Bs[0][lkq+2][lm]=b0.z; Bs[0][lkq+3][lm]=b0.w;
        Bs[0][lkq+4][lm]=b1.x; Bs[0][lkq+5][lm]=b1.y; Bs[0][lkq+6][lm]=b1.z; Bs[0][lkq+7][lm]=b1.w;
    }
    __syncthreads();

    int cur = 0;
    for (int t = 0; t < 32; t++){
        float4 na0, na1, nb0, nb1;
        if (t < 31){
            int k0 = (t+1)*16;
            na0 = av ? *(const float4*)(Arow + k0)     : make_float4(0,0,0,0);
            na1 = av ? *(const float4*)(Arow + k0 + 4) : make_float4(0,0,0,0);
            nb0 = *(const float4*)(Brow + k0);
            nb1 = *(const float4*)(Brow + k0 + 4);
        }
        const float* as = &As[cur][0][ty*16];
        const float* bs = &Bs[cur][0][tx*4];
        #pragma unroll
        for (int kk = 0; kk < 16; kk++){
            ulonglong2 a01 = *(const ulonglong2*)(as + kk*132);
            ulonglong2 a23 = *(const ulonglong2*)(as + kk*132 + 4);
            ulonglong2 a45 = *(const ulonglong2*)(as + kk*132 + 8);
            ulonglong2 a67 = *(const ulonglong2*)(as + kk*132 + 12);
            float4 bf = *(const float4*)(bs + kk*132);
            ull b0 = pk2(bf.x, bf.x), b1 = pk2(bf.y, bf.y);
            ull b2 = pk2(bf.z, bf.z), b3 = pk2(bf.w, bf.w);
            ull ap[8] = {a01.x, a01.y, a23.x, a23.y, a45.x, a45.y, a67.x, a67.y};
            #pragma unroll
            for (int i = 0; i < 8; i++){
                fma2(acc[i][0], ap[i], b0);
                fma2(acc[i][1], ap[i], b1);
                fma2(acc[i][2], ap[i], b2);
                fma2(acc[i][3], ap[i], b3);
            }
        }
        if (t < 31){
            int nx = cur ^ 1;
            As[nx][lkq+0][lm]=na0.x; As[nx][lkq+1][lm]=na0.y; As[nx][lkq+2][lm]=na0.z; As[nx][lkq+3][lm]=na0.w;
            As[nx][lkq+4][lm]=na1.x; As[nx][lkq+5][lm]=na1.y; As[nx][lkq+6][lm]=na1.z; As[nx][lkq+7][lm]=na1.w;
            Bs[nx][lkq+0][lm]=nb0.x; Bs[nx][lkq+1][lm]=nb0.y; Bs[nx][lkq+2][lm]=nb0.z; Bs[nx][lkq+3][lm]=nb0.w;
            Bs[nx][lkq+4][lm]=nb1.x; Bs[nx][lkq+5][lm]=nb1.y; Bs[nx][lkq+6][lm]=nb1.z; Bs[nx][lkq+7][lm]=nb1.w;
        }
        __syncthreads();
        cur ^= 1;
    }

    float bb[4];
    #pragma unroll
    for (int c = 0; c < 4; c++) bb[c] = __ldg(bias + n0 + tx*4 + c);

    #pragma unroll
    for (int mp = 0; mp < 8; mp++){
        float4 r0, r1;
        upk2(acc[mp][0], r0.x, r1.x);
        upk2(acc[mp][1], r0.y, r1.y);
        upk2(acc[mp][2], r0.z, r1.z);
        upk2(acc[mp][3], r0.w, r1.w);
        r0.x += bb[0]; r0.y += bb[1]; r0.z += bb[2]; r0.w += bb[3];
        r1.x += bb[0]; r1.y += bb[1]; r1.z += bb[2]; r1.w += bb[3];
        #pragma unroll
        for (int h = 0; h < 2; h++){
            int row = m0 + ty*16 + 2*mp + h;
            if (row < M){
                float* dst;
                if (SCATTER){
                    int b = row & 15, s = row >> 4;
                    dst = C + (size_t)b*Tsz*Vsz + (size_t)(s+1)*Vsz + n0 + tx*4;
                } else {
                    dst = C + (size_t)row*ldc + n0 + tx*4;
                }
                *(float4*)dst = h ? r1 : r0;
            }
        }
    }
}

/* ---------- persistent recurrence: 64 CTAs x 512 thr, PROVEN master barrier ---------- */
__device__ __forceinline__ void gbar(int p){
    __syncthreads();
    if (blockIdx.x == 0){
        if (threadIdx.x < 32){
            if (threadIdx.x == 0){ __threadfence(); g_flags[0] = p; }
            __syncwarp();
            int i0 = threadIdx.x*2;
            for (;;){
                int a = g_flags[i0], b = g_flags[i0+1];
                if (__all_sync(0xffffffffu, min(a,b) >= p)) break;
            }
            if (threadIdx.x == 0){ __threadfence(); g_rel = p; }
        }
    } else if (threadIdx.x == 0){
        __threadfence();
        g_flags[blockIdx.x] = p;
        while (g_rel < p) {}
        __threadfence();
    }
    __syncthreads();
}

#define SHP 18
__device__ __forceinline__ void stageSH(float* SH, const float* src){
    __syncthreads();
    for (int i = threadIdx.x; i < Hsz*Bsz; i += 512)
        SH[(i>>4)*SHP + (i&15)] = __ldcg(src + i);
    __syncthreads();
}

/* warp: 2 rows x 16 batches (as 8 pairs), K=512; SH = rhs [k][b] pad SHP */
__device__ __forceinline__ void bgemm2p(const float* __restrict__ w0r, const float* __restrict__ w1r,
                                        float bias0, float bias1,
                                        float* o0, float* o1, int st,
                                        const float* SH, int lane)
{
    ull ap0[8], ap1[8];
    #pragma unroll
    for (int j = 0; j < 8; j++){ ap0[j] = 0ull; ap1[j] = 0ull; }
    #pragma unroll 8
    for (int ki = 0; ki < 16; ki++){
        int k = ki*32 + lane;
        float w0 = __ldg(w0r + k), w1 = __ldg(w1r + k);
        ull wp0 = pk2(w0, w0), wp1 = pk2(w1, w1);
        const ull* hv = (const ull*)(SH + k*SHP);
        #pragma unroll
        for (int j = 0; j < 8; j++){
            ull h2 = hv[j];
            fma2(ap0[j], wp0, h2);
            fma2(ap1[j], wp1, h2);
        }
    }
    #pragma unroll
    for (int j = 0; j < 8; j++){ ap0[j] = wred64(ap0[j]); ap1[j] = wred64(ap1[j]); }
    if (lane < 8){
        float lo, hi; upk2(ap0[lane], lo, hi);
        __stcg(o0 + (2*lane)*st,   lo + bias0);
        __stcg(o0 + (2*lane+1)*st, hi + bias0);
    } else if (lane < 16){
        int j = lane - 8;
        float lo, hi; upk2(ap1[j], lo, hi);
        __stcg(o1 + (2*j)*st,   lo + bias1);
        __stcg(o1 + (2*j+1)*st, hi + bias1);
    }
}

__global__ void __launch_bounds__(512)
k_recur(const float* __restrict__ enc, const int* __restrict__ mask,
        const float* __restrict__ Wq,  const float* __restrict__ bq,
        const float* __restrict__ Whh, const float* __restrict__ bhh,
        const float* __restrict__ Wih, const float* __restrict__ Wc,
        const float* __restrict__ bc)
{
    __shared__ __align__(16) float SH[Hsz*SHP];
    int tid = threadIdx.x;
    int lane = tid & 31;
    int wg = blockIdx.x*16 + (tid >> 5);       /* 0..1023 */
    float bcv = __ldg(bc);
    int p = 0;

    for (int s = 0; s < STEPS; s++){
        /* ---- phase A: q = h@Wq^T+bq ; gh = h@Whh^T+bhh (f32x2 pairs) ---- */
        stageSH(SH, g_hT + (s&1)*(Hsz*Bsz));
        {
            int r0 = 2*wg;
            if (r0 < 512){
                bgemm2p(Wq + (size_t)r0*512, Wq + (size_t)(r0+1)*512,
                        __ldg(bq+r0), __ldg(bq+r0+1),
                        g_q + r0, g_q + r0 + 1, 512, SH, lane);
            } else {
                int g = r0 - 512;
                bgemm2p(Whh + (size_t)g*512, Whh + (size_t)(g+1)*512,
                        __ldg(bhh+g), __ldg(bhh+g+1),
                        g_gh + g, g_gh + g + 1, 1536, SH, lane);
            }
        }
        gbar(++p);

        /* ---- phase B: scores (warp = 2 (b,t) rows) ---- */
        {
            int pr0 = 2*wg;
            int b = pr0 >> 7, t0 = pr0 & 127;
            const float* qp = g_q + b*Hsz;
            float qk[16], wv[16];
            #pragma unroll
            for (int ki = 0; ki < 16; ki++){
                int k = ki*32 + lane;
                qk[ki] = __ldcg(qp + k);
                wv[ki] = __ldg(Wc + k);
            }
            #pragma unroll
            for (int i = 0; i < 2; i++){
                int t = t0 + i;
                const float* vp = g_vt + ((size_t)b*Tsz + t)*Hsz;
                float vv[16];
                #pragma unroll
                for (int ki = 0; ki < 16; ki++) vv[ki] = __ldg(vp + ki*32 + lane);
                float acc = 0.f;
                #pragma unroll
                for (int ki = 0; ki < 16; ki++) acc += wv[ki] * ftanh(qk[ki] + vv[ki]);
                acc = wred(acc);
                if (lane == 0){
                    float sc = acc + bcv;
                    if (__ldg(mask + b*Tsz + t) == 0) sc = -FLT_MAX;
                    __stcg(g_scores + b*Tsz + t, sc);
                }
            }
        }
        gbar(++p);

        /* ---- phase C: softmax + ctx (2 units per CTA; unit = (b, 64-dim chunk)) ---- */
        {
            int su = tid >> 8;                  /* 0..1 */
            int stid = tid & 255;
            int slane = stid & 31;
            int unit = blockIdx.x*2 + su;       /* 0..127 */
            int b = unit >> 3, hb = (unit & 7)*64;
            float* Ch = SH + su*1024;
            __syncthreads();
            float sv = -FLT_MAX;
            if (stid < 128){
                sv = __ldcg(g_scores + b*Tsz + stid);
                float m = wmax(sv);
                if (slane == 0) Ch[128 + (stid>>5)] = m;
            }
            __syncthreads();
            if (stid == 0)
                Ch[136] = fmaxf(fmaxf(Ch[128],Ch[129]), fmaxf(Ch[130],Ch[131]));
            __syncthreads();
            if (stid < 128){
                float e = __expf(sv - Ch[136]);
                Ch[stid] = e;
                float sm = wred(e);
                if (slane == 0) Ch[140 + (stid>>5)] = sm;
            }
            __syncthreads();
            if (stid == 0)
                Ch[137] = __fdividef(1.f, Ch[140]+Ch[141]+Ch[142]+Ch[143]);
            __syncthreads();
            float inv = Ch[137];
            int d = stid & 63, tq = stid >> 6;
            const float* ep = enc + ((size_t)b*Tsz + tq*32)*Hsz + hb + d;
            float part = 0.f;
            #pragma unroll 8
            for (int i = 0; i < 32; i++)
                part += Ch[tq*32 + i] * __ldg(ep + (size_t)i*Hsz);
            Ch[256 + tq*64 + d] = part;
            __syncthreads();
            if (stid < 64){
                float v = (Ch[256+stid] + Ch[320+stid] + Ch[384+stid] + Ch[448+stid]) * inv;
                __stcg(g_ctxT + (hb + stid)*16 + b, v);
            }
        }
        gbar(++p);

        /* ---- phase D: gic + GRU update (f32x2 pairs) ---- */
        stageSH(SH, g_ctxT);
        {
            int j = wg >> 1, bh = (wg & 1)*8;
            ull ar[4], az[4], an[4];
            #pragma unroll
            for (int q = 0; q < 4; q++){ ar[q]=0ull; az[q]=0ull; an[q]=0ull; }
            const float* wr = Wih + (size_t)j*1024 + 512;
            const float* wz = Wih + (size_t)(j+512)*1024 + 512;
            const float* wn = Wih + (size_t)(j+1024)*1024 + 512;
            #pragma unroll 8
            for (int ki = 0; ki < 16; ki++){
                int k = ki*32 + lane;
                float r_ = __ldg(wr + k), z_ = __ldg(wz + k), n_ = __ldg(wn + k);
                ull rp = pk2(r_, r_), zp = pk2(z_, z_), np = pk2(n_, n_);
                const ull* hv = (const ull*)(SH + k*SHP + bh);
                #pragma unroll
                for (int q = 0; q < 4; q++){
                    ull c2 = hv[q];
                    fma2(ar[q], rp, c2);
                    fma2(az[q], zp, c2);
                    fma2(an[q], np, c2);
                }
            }
            #pragma unroll
            for (int q = 0; q < 4; q++){
                ar[q] = wred64(ar[q]); az[q] = wred64(az[q]); an[q] = wred64(an[q]);
            }
            if (lane < 4){
                float vr0, vr1, vz0, vz1, vn0, vn1;
                upk2(ar[lane], vr0, vr1);
                upk2(az[lane], vz0, vz1);
                upk2(an[lane], vn0, vn1);
                #pragma unroll
                for (int h = 0; h < 2; h++){
                    int bb = bh + 2*lane + h;
                    float v0 = h ? vr1 : vr0;
                    float v1 = h ? vz1 : vz0;
                    float v2 = h ? vn1 : vn0;
                    size_t m = (size_t)s*16 + bb;
                    float gir = __ldg(g_gix + m*1536 + j)        + v0;
                    float giz = __ldg(g_gix + m*1536 + 512 + j)  + v1;
                    float gin = __ldg(g_gix + m*1536 + 1024 + j) + v2;
                    float ghr = __ldcg(g_gh + bb*1536 + j);
                    float ghz = __ldcg(g_gh + bb*1536 + 512 + j);
                    float ghn = __ldcg(g_gh + bb*1536 + 1024 + j);
                    float hp  = __ldcg(g_hT + (s&1)*(Hsz*Bsz) + j*16 + bb);
                    float rr = fsig(gir + ghr);
                    float zz = fsig(giz + ghz);
                    float nn = ftanh(gin + rr*ghn);
                    float hN = (1.0f - zz)*nn + zz*hp;
                    __stcg(g_Hs + m*Hsz + j, hN);
                    __stcg(g_hT + ((s+1)&1)*(Hsz*Bsz) + j*16 + bb, hN);
                }
            }
        }
        gbar(++p);
    }
}

/* ---------- launch ---------- */
extern "C" void kernel_launch(void* const* d_in, const int* in_sizes, int n_in,
                              void* d_out, int out_size)
{
    const float* enc  = (const float*)d_in[0];
    const float* eh   = (const float*)d_in[1];
    const int*   msk  = (const int*)  d_in[2];
    const int*   tgt  = (const int*)  d_in[3];
    const float* emb  = (const float*)d_in[4];
    const float* Wq   = (const float*)d_in[5];
    const float* bq   = (const float*)d_in[6];
    const float* Wv   = (const float*)d_in[7];
    const float* bv   = (const float*)d_in[8];
    const float* Wc   = (const float*)d_in[9];
    const float* bc   = (const float*)d_in[10];
    const float* Wih  = (const float*)d_in[11];
    const float* Whh  = (const float*)d_in[12];
    const float* bih  = (const float*)d_in[13];
    const float* bhh  = (const float*)d_in[14];
    const float* Wo   = (const float*)d_in[15];
    const float* bo   = (const float*)d_in[16];
    float* out = (float*)d_out;

    float *p_vt, *p_xe, *p_gix, *p_Hs;
    cudaGetSymbolAddress((void**)&p_vt,  g_vt);
    cudaGetSymbolAddress((void**)&p_xe,  g_xe);
    cudaGetSymbolAddress((void**)&p_gix, g_gix);
    cudaGetSymbolAddress((void**)&p_Hs,  g_Hs);

    k_h0<<<32, 256>>>(eh);
    k_gather<<<MR, 256>>>(emb, tgt);

    /* vt = enc @ Wv^T + bv : M=2048 N=512 */
    k_gemm<false><<<dim3(16,4), 256>>>(enc, Wv, bv, p_vt, Bsz*Tsz, 512, 512);
    /* gix = xe @ Wih[:, :H]^T + bih : M=2032 N=1536 (ldb = 2H = 1024) */
    k_gemm<false><<<dim3(16,12), 256>>>(p_xe, Wih, bih, p_gix, MR, 1024, 1536);

    k_zero<<<2000, 256>>>(out);
    k_recur<<<NB, 512>>>(enc, msk, Wq, bq, Whh, bhh, Wih, Wc, bc);

    /* logits = Hs @ Wo^T + bo, scattered into out[b, s+1, :] : M=2032 N=32000 */
    k_gemm<true><<<dim3(16,250), 256>>>(p_Hs, Wo, bo, out, MR, 512, 0);

    if (out_size >= Bsz*Tsz*Vsz + Bsz*Hsz)
        k_tail<<<32, 256>>>(out);
}

// round 17
// speedup vs baseline: 1.9909x; 1.0971x over previous
#include <cuda_runtime.h>
#include <cuda_bf16.h>
#include <math.h>
#include <float.h>

#define Bsz 16
#define Tsz 128
#define Hsz 512
#define Vsz 32000
#define STEPS 127
#define MR (STEPS*Bsz)   /* 2032 */
#define NB 64
#define KP 1536          /* split-K: [hi|hi|lo] x [hi|lo|hi] */

/* ---------- device scratch ---------- */
__device__ float g_vt[Bsz*Tsz*Hsz];
__device__ float g_xe[MR*Hsz];
__device__ float g_gix[MR*3*Hsz];
__device__ float g_Hs[MR*Hsz];
__device__ float g_q[Bsz*Hsz];
__device__ float g_gh[Bsz*3*Hsz];
__device__ float g_scores[Bsz*Tsz];
__device__ float g_ctxT[Hsz*Bsz];
__device__ float g_hT[2*Hsz*Bsz];
__device__ volatile int g_flags[NB];
__device__ volatile int g_rel;
__device__ __nv_bfloat16 g_ah[2048*KP];    /* A' rows padded to 2048 */
__device__ __nv_bfloat16 g_bh[(size_t)Vsz*KP];  /* B' 32000 x 1536 */

/* ---------- helpers ---------- */
typedef unsigned long long ull;
__device__ __forceinline__ ull pk2(float lo, float hi){
    ull r; asm("mov.b64 %0,{%1,%2};" : "=l"(r) : "f"(lo), "f"(hi)); return r;
}
__device__ __forceinline__ void upk2(ull v, float& lo, float& hi){
    asm("mov.b64 {%0,%1},%2;" : "=f"(lo), "=f"(hi) : "l"(v));
}
__device__ __forceinline__ void fma2(ull& d, ull a, ull b){
    asm("fma.rn.f32x2 %0,%1,%2,%0;" : "+l"(d) : "l"(a), "l"(b));
}
__device__ __forceinline__ ull addp(ull a, ull b){
    ull r; asm("add.rn.f32x2 %0,%1,%2;" : "=l"(r) : "l"(a), "l"(b)); return r;
}
__device__ __forceinline__ ull wred64(ull v){
    #pragma unroll
    for (int o = 16; o > 0; o >>= 1)
        v = addp(v, __shfl_xor_sync(0xffffffffu, v, o));
    return v;
}
__device__ __forceinline__ float wred(float v){
    #pragma unroll
    for (int o = 16; o > 0; o >>= 1) v += __shfl_xor_sync(0xffffffffu, v, o);
    return v;
}
__device__ __forceinline__ float wmax(float v){
    #pragma unroll
    for (int o = 16; o > 0; o >>= 1) v = fmaxf(v, __shfl_xor_sync(0xffffffffu, v, o));
    return v;
}
__device__ __forceinline__ float ftanh(float x){
    float cx = fminf(fmaxf(x, -9.f), 9.f);
    float e = __expf(2.f*cx);
    return __fdividef(e - 1.f, e + 1.f);
}
__device__ __forceinline__ float fsig(float x){
    float cx = fminf(fmaxf(x, -30.f), 30.f);
    return __fdividef(1.f, 1.f + __expf(-cx));
}

/* ---------- init ---------- */
__global__ void k_h0(const float* __restrict__ eh){
    int i = blockIdx.x*256 + threadIdx.x;
    if (i < Hsz*Bsz){
        int b = i >> 9, k = i & 511;
        g_hT[k*16 + b] = eh[i];
    }
    if (blockIdx.x == 0 && threadIdx.x < NB) g_flags[threadIdx.x] = 0;
    if (blockIdx.x == 0 && threadIdx.x == 0) g_rel = 0;
}

__global__ void k_gather(const float* __restrict__ emb, const int* __restrict__ tgt){
    int m = blockIdx.x;
    int s = m >> 4, b = m & 15;
    int tok = (s == 0) ? 1 : tgt[b*Tsz + s];
    const float4* src = (const float4*)(emb + (size_t)tok*Hsz);
    float4* dst = (float4*)(g_xe + (size_t)m*Hsz);
    for (int i = threadIdx.x; i < Hsz/4; i += blockDim.x) dst[i] = src[i];
}

__global__ void k_zero(float* __restrict__ out){
    int i = blockIdx.x*256 + threadIdx.x;
    int b = i / Vsz, v = i - b*Vsz;
    out[(size_t)b*Tsz*Vsz + v] = 0.0f;
}

__global__ void k_tail(float* __restrict__ out){
    int i = blockIdx.x*256 + threadIdx.x;
    int b = i >> 9, k = i & 511;
    out[(size_t)Bsz*Tsz*Vsz + i] = g_Hs[(size_t)((STEPS-1)*16 + b)*Hsz + k];
}

/* ---------- split-bf16 conversions ---------- */
__global__ void k_cvtA(void){
    int r = blockIdx.x;                       /* 0..2047 */
    for (int c = threadIdx.x; c < Hsz; c += 256){
        float a = (r < MR) ? g_Hs[(size_t)r*Hsz + c] : 0.f;
        __nv_bfloat16 h = __float2bfloat16(a);
        __nv_bfloat16 l = __float2bfloat16(a - __bfloat162float(h));
        size_t base = (size_t)r*KP;
        g_ah[base + c] = h;
        g_ah[base + 512 + c] = h;
        g_ah[base + 1024 + c] = l;
    }
}
__global__ void k_cvtB(const float* __restrict__ Wo){
    int r = blockIdx.x;                       /* 0..31999 */
    for (int c = threadIdx.x; c < Hsz; c += 128){
        float a = Wo[(size_t)r*Hsz + c];
        __nv_bfloat16 h = __float2bfloat16(a);
        __nv_bfloat16 l = __float2bfloat16(a - __bfloat162float(h));
        size_t base = (size_t)r*KP;
        g_bh[base + c] = h;
        g_bh[base + 512 + c] = l;
        g_bh[base + 1024 + c] = h;
    }
}

/* ---------- bf16 HMMA GEMM (mma.sync m16n8k16): out[b,s+1,:] = Hs@Wo^T + bo ----
   128x128 tile, 8 warps, warp = 64x32 (4x4 frags), K=1536, 48 stages of 32. */
#define KB 32
#define APAD 40

__global__ void __launch_bounds__(256)
k_hmma(const float* __restrict__ bias, float* __restrict__ out)
{
    __shared__ __align__(16) __nv_bfloat16 As[2][128][APAD];
    __shared__ __align__(16) __nv_bfloat16 Bs[2][128][APAD];
    int tid = threadIdx.x;
    int lane = tid & 31, wid = tid >> 5;
    int wm = wid >> 2, wn = wid & 3;
    int g = lane >> 2, tg = lane & 3;
    int m0 = blockIdx.x*128, n0 = blockIdx.y*128;

    const __nv_bfloat16* Ab = g_ah + (size_t)m0*KP;
    const __nv_bfloat16* Bb = g_bh + (size_t)n0*KP;

    float acc[4][4][4];
    #pragma unroll
    for (int i = 0; i < 4; i++)
        #pragma unroll
        for (int j = 0; j < 4; j++)
            #pragma unroll
            for (int q = 0; q < 4; q++) acc[i][j][q] = 0.f;

    int c0i = tid, c1i = tid + 256;
    int r0 = c0i >> 2, q0 = (c0i & 3)*8;
    int r1 = c1i >> 2, q1 = (c1i & 3)*8;

    /* prologue: stage 0 */
    *(uint4*)&As[0][r0][q0] = *(const uint4*)(Ab + (size_t)r0*KP + q0);
    *(uint4*)&As[0][r1][q1] = *(const uint4*)(Ab + (size_t)r1*KP + q1);
    *(uint4*)&Bs[0][r0][q0] = *(const uint4*)(Bb + (size_t)r0*KP + q0);
    *(uint4*)&Bs[0][r1][q1] = *(const uint4*)(Bb + (size_t)r1*KP + q1);
    __syncthreads();

    for (int s = 0; s < 48; s++){
        uint4 na0, na1, nb0, nb1;
        if (s < 47){
            int k0 = (s+1)*KB;
            na0 = *(const uint4*)(Ab + (size_t)r0*KP + k0 + q0);
            na1 = *(const uint4*)(Ab + (size_t)r1*KP + k0 + q1);
            nb0 = *(const uint4*)(Bb + (size_t)r0*KP + k0 + q0);
            nb1 = *(const uint4*)(Bb + (size_t)r1*KP + k0 + q1);
        }
        int buf = s & 1;
        #pragma unroll
        for (int ks = 0; ks < 2; ks++){
            int k = ks*16 + tg*2;
            unsigned a[4][4], b[4][2];
            #pragma unroll
            for (int mf = 0; mf < 4; mf++){
                int r = wm*64 + mf*16 + g;
                a[mf][0] = *(const unsigned*)&As[buf][r][k];
                a[mf][1] = *(const unsigned*)&As[buf][r+8][k];
                a[mf][2] = *(const unsigned*)&As[buf][r][k+8];
                a[mf][3] = *(const unsigned*)&As[buf][r+8][k+8];
            }
            #pragma unroll
            for (int nf = 0; nf < 4; nf++){
                int n = wn*32 + nf*8 + g;
                b[nf][0] = *(const unsigned*)&Bs[buf][n][k];
                b[nf][1] = *(const unsigned*)&Bs[buf][n][k+8];
            }
            #pragma unroll
            for (int mf = 0; mf < 4; mf++){
                #pragma unroll
                for (int nf = 0; nf < 4; nf++){
                    asm volatile(
                        "mma.sync.aligned.m16n8k16.row.col.f32.bf16.bf16.f32 "
                        "{%0,%1,%2,%3}, {%4,%5,%6,%7}, {%8,%9}, {%0,%1,%2,%3};"
                        : "+f"(acc[mf][nf][0]), "+f"(acc[mf][nf][1]),
                          "+f"(acc[mf][nf][2]), "+f"(acc[mf][nf][3])
                        : "r"(a[mf][0]), "r"(a[mf][1]), "r"(a[mf][2]), "r"(a[mf][3]),
                          "r"(b[nf][0]), "r"(b[nf][1]));
                }
            }
        }
        if (s < 47){
            int nx = buf ^ 1;
            *(uint4*)&As[nx][r0][q0] = na0;
            *(uint4*)&As[nx][r1][q1] = na1;
            *(uint4*)&Bs[nx][r0][q0] = nb0;
            *(uint4*)&Bs[nx][r1][q1] = nb1;
        }
        __syncthreads();
    }

    /* epilogue: scatter with bias */
    #pragma unroll
    for (int mf = 0; mf < 4; mf++){
        #pragma unroll
        for (int nf = 0; nf < 4; nf++){
            int col = n0 + wn*32 + nf*8 + tg*2;
            float bv0 = __ldg(bias + col), bv1 = __ldg(bias + col + 1);
            int rowA = m0 + wm*64 + mf*16 + g;
            if (rowA < MR){
                int b = rowA & 15, st = rowA >> 4;
                float* dst = out + (size_t)b*Tsz*Vsz + (size_t)(st+1)*Vsz + col;
                *(float2*)dst = make_float2(acc[mf][nf][0] + bv0, acc[mf][nf][1] + bv1);
            }
            int rowB = rowA + 8;
            if (rowB < MR){
                int b = rowB & 15, st = rowB >> 4;
                float* dst = out + (size_t)b*Tsz*Vsz + (size_t)(st+1)*Vsz + col;
                *(float2*)dst = make_float2(acc[mf][nf][2] + bv0, acc[mf][nf][3] + bv1);
            }
        }
    }
}

/* ---------- fp32 FFMA2 GEMM (precompute): C = A@B^T + bias ---------- */
template<bool SCATTER>
__global__ void __launch_bounds__(256, 2)
k_gemm(const float* __restrict__ A, const float* __restrict__ B,
       const float* __restrict__ bias, float* __restrict__ C,
       int M, int ldb, int ldc)
{
    __shared__ __align__(16) float As[2][16][132];
    __shared__ __align__(16) float Bs[2][16][132];
    int tid = threadIdx.x;
    int tx = tid & 31, ty = tid >> 5;
    int m0 = blockIdx.x*128, n0 = blockIdx.y*128;
    int lm = tid >> 1, lkq = (tid & 1)*8;

    ull acc[8][4];
    #pragma unroll
    for (int i = 0; i < 8; i++){
        #pragma unroll
        for (int j = 0; j < 4; j++) acc[i][j] = 0ull;
    }

    bool av = (m0 + lm) < M;
    const float* Arow = A + (size_t)(m0 + lm)*512 + lkq;
    const float* Brow = B + (size_t)(n0 + lm)*ldb + lkq;

    {
        float4 a0 = av ? *(const float4*)(Arow)     : make_float4(0,0,0,0);
        float4 a1 = av ? *(const float4*)(Arow + 4) : make_float4(0,0,0,0);
        float4 b0 = *(const float4*)(Brow);
        float4 b1 = *(const float4*)(Brow + 4);
        As[0][lkq+0][lm]=a0.x; As[0][lkq+1][lm]=a0.y; As[0][lkq+2][lm]=a0.z; As[0][lkq+3][lm]=a0.w;
        As[0][lkq+4][lm]=a1.x; As[0][lkq+5][lm]=a1.y; As[0][lkq+6][lm]=a1.z; As[0][lkq+7][lm]=a1.w;
        Bs[0][lkq+0][lm]=b0.x; Bs[0][lkq+1][lm]=b0.y; Bs[0][lkq+2][lm]=b0.z; Bs[0][lkq+3][lm]=b0.w;
        Bs[0][lkq+4][lm]=b1.x; Bs[0][lkq+5][lm]=b1.y; Bs[0][lkq+6][lm]=b1.z; Bs[0][lkq+7][lm]=b1.w;
    }
    __syncthreads();

    int cur = 0;
    for (int t = 0; t < 32; t++){
        float4 na0, na1, nb0, nb1;
        if (t < 31){
            int k0 = (t+1)*16;
            na0 = av ? *(const float4*)(Arow + k0)     : make_float4(0,0,0,0);
            na1 = av ? *(const float4*)(Arow + k0 + 4) : make_float4(0,0,0,0);
            nb0 = *(const float4*)(Brow + k0);
            nb1 = *(const float4*)(Brow + k0 + 4);
        }
        const float* as = &As[cur][0][ty*16];
        const float* bs = &Bs[cur][0][tx*4];
        #pragma unroll
        for (int kk = 0; kk < 16; kk++){
            ulonglong2 a01 = *(const ulonglong2*)(as + kk*132);
            ulonglong2 a23 = *(const ulonglong2*)(as + kk*132 + 4);
            ulonglong2 a45 = *(const ulonglong2*)(as + kk*132 + 8);
            ulonglong2 a67 = *(const ulonglong2*)(as + kk*132 + 12);
            float4 bf = *(const float4*)(bs + kk*132);
            ull b0 = pk2(bf.x, bf.x), b1 = pk2(bf.y, bf.y);
            ull b2 = pk2(bf.z, bf.z), b3 = pk2(bf.w, bf.w);
            ull ap[8] = {a01.x, a01.y, a23.x, a23.y, a45.x, a45.y, a67.x, a67.y};
            #pragma unroll
            for (int i = 0; i < 8; i++){
                fma2(acc[i][0], ap[i], b0);
                fma2(acc[i][1], ap[i], b1);
                fma2(acc[i][2], ap[i], b2);
                fma2(acc[i][3], ap[i], b3);
            }
        }
        if (t < 31){
            int nx = cur ^ 1;
            As[nx][lkq+0][lm]=na0.x; As[nx][lkq+1][lm]=na0.y; As[nx][lkq+2][lm]=na0.z; As[nx][lkq+3][lm]=na0.w;
            As[nx][lkq+4][lm]=na1.x; As[nx][lkq+5][lm]=na1.y; As[nx][lkq+6][lm]=na1.z; As[nx][lkq+7][lm]=na1.w;
            Bs[nx][lkq+0][lm]=nb0.x; Bs[nx][lkq+1][lm]=nb0.y; Bs[nx][lkq+2][lm]=nb0.z; Bs[nx][lkq+3][lm]=nb0.w;
            Bs[nx][lkq+4][lm]=nb1.x; Bs[nx][lkq+5][lm]=nb1.y; Bs[nx][lkq+6][lm]=nb1.z; Bs[nx][lkq+7][lm]=nb1.w;
        }
        __syncthreads();
        cur ^= 1;
    }

    float bb[4];
    #pragma unroll
    for (int c = 0; c < 4; c++) bb[c] = __ldg(bias + n0 + tx*4 + c);

    #pragma unroll
    for (int mp = 0; mp < 8; mp++){
        float4 r0v, r1v;
        upk2(acc[mp][0], r0v.x, r1v.x);
        upk2(acc[mp][1], r0v.y, r1v.y);
        upk2(acc[mp][2], r0v.z, r1v.z);
        upk2(acc[mp][3], r0v.w, r1v.w);
        r0v.x += bb[0]; r0v.y += bb[1]; r0v.z += bb[2]; r0v.w += bb[3];
        r1v.x += bb[0]; r1v.y += bb[1]; r1v.z += bb[2]; r1v.w += bb[3];
        #pragma unroll
        for (int h = 0; h < 2; h++){
            int row = m0 + ty*16 + 2*mp + h;
            if (row < M){
                float* dst;
                if (SCATTER){
                    int b = row & 15, s = row >> 4;
                    dst = C + (size_t)b*Tsz*Vsz + (size_t)(s+1)*Vsz + n0 + tx*4;
                } else {
                    dst = C + (size_t)row*ldc + n0 + tx*4;
                }
                *(float4*)dst = h ? r1v : r0v;
            }
        }
    }
}

/* ---------- persistent recurrence: 64 CTAs x 512 thr, master barrier ---------- */
__device__ __forceinline__ void gbar(int p){
    __syncthreads();
    if (blockIdx.x == 0){
        if (threadIdx.x < 32){
            if (threadIdx.x == 0){ __threadfence(); g_flags[0] = p; }
            __syncwarp();
            int i0 = threadIdx.x*2;
            for (;;){
                int a = g_flags[i0], b = g_flags[i0+1];
                if (__all_sync(0xffffffffu, min(a,b) >= p)) break;
            }
            if (threadIdx.x == 0){ __threadfence(); g_rel = p; }
        }
    } else if (threadIdx.x == 0){
        __threadfence();
        g_flags[blockIdx.x] = p;
        while (g_rel < p) {}
        __threadfence();
    }
    __syncthreads();
}

#define SHP 18
__device__ __forceinline__ void stageSH(float* SH, const float* src){
    __syncthreads();
    for (int i = threadIdx.x; i < Hsz*Bsz; i += 512)
        SH[(i>>4)*SHP + (i&15)] = __ldcg(src + i);
    __syncthreads();
}

__device__ __forceinline__ void bgemm2p(const float* __restrict__ w0r, const float* __restrict__ w1r,
                                        float bias0, float bias1,
                                        float* o0, float* o1, int st,
                                        const float* SH, int lane)
{
    ull ap0[8], ap1[8];
    #pragma unroll
    for (int j = 0; j < 8; j++){ ap0[j] = 0ull; ap1[j] = 0ull; }
    #pragma unroll 8
    for (int ki = 0; ki < 16; ki++){
        int k = ki*32 + lane;
        float w0 = __ldg(w0r + k), w1 = __ldg(w1r + k);
        ull wp0 = pk2(w0, w0), wp1 = pk2(w1, w1);
        const ull* hv = (const ull*)(SH + k*SHP);
        #pragma unroll
        for (int j = 0; j < 8; j++){
            ull h2 = hv[j];
            fma2(ap0[j], wp0, h2);
            fma2(ap1[j], wp1, h2);
        }
    }
    #pragma unroll
    for (int j = 0; j < 8; j++){ ap0[j] = wred64(ap0[j]); ap1[j] = wred64(ap1[j]); }
    if (lane < 8){
        float lo, hi; upk2(ap0[lane], lo, hi);
        __stcg(o0 + (2*lane)*st,   lo + bias0);
        __stcg(o0 + (2*lane+1)*st, hi + bias0);
    } else if (lane < 16){
        int j = lane - 8;
        float lo, hi; upk2(ap1[j], lo, hi);
        __stcg(o1 + (2*j)*st,   lo + bias1);
        __stcg(o1 + (2*j+1)*st, hi + bias1);
    }
}

__global__ void __launch_bounds__(512)
k_recur(const float* __restrict__ enc, const int* __restrict__ mask,
        const float* __restrict__ Wq,  const float* __restrict__ bq,
        const float* __restrict__ Whh, const float* __restrict__ bhh,
        const float* __restrict__ Wih, const float* __restrict__ Wc,
        const float* __restrict__ bc)
{
    __shared__ __align__(16) float SH[Hsz*SHP];
    int tid = threadIdx.x;
    int lane = tid & 31;
    int wg = blockIdx.x*16 + (tid >> 5);
    float bcv = __ldg(bc);
    int p = 0;

    for (int s = 0; s < STEPS; s++){
        /* ---- phase A ---- */
        stageSH(SH, g_hT + (s&1)*(Hsz*Bsz));
        {
            int r0 = 2*wg;
            if (r0 < 512){
                bgemm2p(Wq + (size_t)r0*512, Wq + (size_t)(r0+1)*512,
                        __ldg(bq+r0), __ldg(bq+r0+1),
                        g_q + r0, g_q + r0 + 1, 512, SH, lane);
            } else {
                int g = r0 - 512;
                bgemm2p(Whh + (size_t)g*512, Whh + (size_t)(g+1)*512,
                        __ldg(bhh+g), __ldg(bhh+g+1),
                        g_gh + g, g_gh + g + 1, 1536, SH, lane);
            }
        }
        gbar(++p);

        /* ---- phase B: scores ---- */
        {
            int pr0 = 2*wg;
            int b = pr0 >> 7, t0 = pr0 & 127;
            const float* qp = g_q + b*Hsz;
            float qk[16], wv[16];
            #pragma unroll
            for (int ki = 0; ki < 16; ki++){
                int k = ki*32 + lane;
                qk[ki] = __ldcg(qp + k);
                wv[ki] = __ldg(Wc + k);
            }
            #pragma unroll
            for (int i = 0; i < 2; i++){
                int t = t0 + i;
                const float* vp = g_vt + ((size_t)b*Tsz + t)*Hsz;
                float vv[16];
                #pragma unroll
                for (int ki = 0; ki < 16; ki++) vv[ki] = __ldg(vp + ki*32 + lane);
                float acc = 0.f;
                #pragma unroll
                for (int ki = 0; ki < 16; ki++) acc += wv[ki] * ftanh(qk[ki] + vv[ki]);
                acc = wred(acc);
                if (lane == 0){
                    float sc = acc + bcv;
                    if (__ldg(mask + b*Tsz + t) == 0) sc = -FLT_MAX;
                    __stcg(g_scores + b*Tsz + t, sc);
                }
            }
        }
        gbar(++p);

        /* ---- phase C: softmax + ctx ---- */
        {
            int su = tid >> 8;
            int stid = tid & 255;
            int slane = stid & 31;
            int unit = blockIdx.x*2 + su;
            int b = unit >> 3, hb = (unit & 7)*64;
            float* Ch = SH + su*1024;
            __syncthreads();
            float sv = -FLT_MAX;
            if (stid < 128){
                sv = __ldcg(g_scores + b*Tsz + stid);
                float m = wmax(sv);
                if (slane == 0) Ch[128 + (stid>>5)] = m;
            }
            __syncthreads();
            if (stid == 0)
                Ch[136] = fmaxf(fmaxf(Ch[128],Ch[129]), fmaxf(Ch[130],Ch[131]));
            __syncthreads();
            if (stid < 128){
                float e = __expf(sv - Ch[136]);
                Ch[stid] = e;
                float sm = wred(e);
                if (slane == 0) Ch[140 + (stid>>5)] = sm;
            }
            __syncthreads();
            if (stid == 0)
                Ch[137] = __fdividef(1.f, Ch[140]+Ch[141]+Ch[142]+Ch[143]);
            __syncthreads();
            float inv = Ch[137];
            int d = stid & 63, tq = stid >> 6;
            const float* ep = enc + ((size_t)b*Tsz + tq*32)*Hsz + hb + d;
            float part = 0.f;
            #pragma unroll 8
            for (int i = 0; i < 32; i++)
                part += Ch[tq*32 + i] * __ldg(ep + (size_t)i*Hsz);
            Ch[256 + tq*64 + d] = part;
            __syncthreads();
            if (stid < 64){
                float v = (Ch[256+stid] + Ch[320+stid] + Ch[384+stid] + Ch[448+stid]) * inv;
                __stcg(g_ctxT + (hb + stid)*16 + b, v);
            }
        }
        gbar(++p);

        /* ---- phase D ---- */
        stageSH(SH, g_ctxT);
        {
            int j = wg >> 1, bh = (wg & 1)*8;
            ull ar[4], az[4], an[4];
            #pragma unroll
            for (int q = 0; q < 4; q++){ ar[q]=0ull; az[q]=0ull; an[q]=0ull; }
            const float* wr = Wih + (size_t)j*1024 + 512;
            const float* wz = Wih + (size_t)(j+512)*1024 + 512;
            const float* wn = Wih + (size_t)(j+1024)*1024 + 512;
            #pragma unroll 8
            for (int ki = 0; ki < 16; ki++){
                int k = ki*32 + lane;
                float r_ = __ldg(wr + k), z_ = __ldg(wz + k), n_ = __ldg(wn + k);
                ull rp = pk2(r_, r_), zp = pk2(z_, z_), np = pk2(n_, n_);
                const ull* hv = (const ull*)(SH + k*SHP + bh);
                #pragma unroll
                for (int q = 0; q < 4; q++){
                    ull c2 = hv[q];
                    fma2(ar[q], rp, c2);
                    fma2(az[q], zp, c2);
                    fma2(an[q], np, c2);
                }
            }
            #pragma unroll
            for (int q = 0; q < 4; q++){
                ar[q] = wred64(ar[q]); az[q] = wred64(az[q]); an[q] = wred64(an[q]);
            }
            if (lane < 4){
                float vr0, vr1, vz0, vz1, vn0, vn1;
                upk2(ar[lane], vr0, vr1);
                upk2(az[lane], vz0, vz1);
                upk2(an[lane], vn0, vn1);
                #pragma unroll
                for (int h = 0; h < 2; h++){
                    int bb = bh + 2*lane + h;
                    float v0 = h ? vr1 : vr0;
                    float v1 = h ? vz1 : vz0;
                    float v2 = h ? vn1 : vn0;
                    size_t m = (size_t)s*16 + bb;
                    float gir = __ldg(g_gix + m*1536 + j)        + v0;
                    float giz = __ldg(g_gix + m*1536 + 512 + j)  + v1;
                    float gin = __ldg(g_gix + m*1536 + 1024 + j) + v2;
                    float ghr = __ldcg(g_gh + bb*1536 + j);
                    float ghz = __ldcg(g_gh + bb*1536 + 512 + j);
                    float ghn = __ldcg(g_gh + bb*1536 + 1024 + j);
                    float hp  = __ldcg(g_hT + (s&1)*(Hsz*Bsz) + j*16 + bb);
                    float rr = fsig(gir + ghr);
                    float zz = fsig(giz + ghz);
                    float nn = ftanh(gin + rr*ghn);
                    float hN = (1.0f - zz)*nn + zz*hp;
                    __stcg(g_Hs + m*Hsz + j, hN);
                    __stcg(g_hT + ((s+1)&1)*(Hsz*Bsz) + j*16 + bb, hN);
                }
            }
        }
        gbar(++p);
    }
}

/* ---------- launch ---------- */
extern "C" void kernel_launch(void* const* d_in, const int* in_sizes, int n_in,
                              void* d_out, int out_size)
{
    const float* enc  = (const float*)d_in[0];
    const float* eh   = (const float*)d_in[1];
    const int*   msk  = (const int*)  d_in[2];
    const int*   tgt  = (const int*)  d_in[3];
    const float* emb  = (const float*)d_in[4];
    const float* Wq   = (const float*)d_in[5];
    const float* bq   = (const float*)d_in[6];
    const float* Wv   = (const float*)d_in[7];
    const float* bv   = (const float*)d_in[8];
    const float* Wc   = (const float*)d_in[9];
    const float* bc   = (const float*)d_in[10];
    const float* Wih  = (const float*)d_in[11];
    const float* Whh  = (const float*)d_in[12];
    const float* bih  = (const float*)d_in[13];
    const float* bhh  = (const float*)d_in[14];
    const float* Wo   = (const float*)d_in[15];
    const float* bo   = (const float*)d_in[16];
    float* out = (float*)d_out;

    float *p_vt, *p_xe, *p_gix;
    cudaGetSymbolAddress((void**)&p_vt,  g_vt);
    cudaGetSymbolAddress((void**)&p_xe,  g_xe);
    cudaGetSymbolAddress((void**)&p_gix, g_gix);

    k_h0<<<32, 256>>>(eh);
    k_gather<<<MR, 256>>>(emb, tgt);

    /* vt = enc @ Wv^T + bv */
    k_gemm<false><<<dim3(16,4), 256>>>(enc, Wv, bv, p_vt, Bsz*Tsz, 512, 512);
    /* gix = xe @ Wih[:, :H]^T + bih */
    k_gemm<false><<<dim3(16,12), 256>>>(p_xe, Wih, bih, p_gix, MR, 1024, 1536);

    k_cvtB<<<Vsz, 128>>>(Wo);
    k_zero<<<2000, 256>>>(out);
    k_recur<<<NB, 512>>>(enc, msk, Wq, bq, Whh, bhh, Wih, Wc, bc);
    k_cvtA<<<2048, 256>>>();

    /* logits via bf16 HMMA split: out[b,s+1,:] = Hs @ Wo^T + bo */
    k_hmma<<<dim3(16,250), 256>>>(bo, out);

    if (out_size >= Bsz*Tsz*Vsz + Bsz*Hsz)
        k_tail<<<32, 256>>>(out);
}